// round 4
// baseline (speedup 1.0000x reference)
#include <cuda_runtime.h>
#include <cstdint>

// ---------------------------------------------------------------------------
// AnalogConv2d: 3x3 s1 p1, N=16 C=128 H=W=56 Cout=256, fp32 + bias.
// ptxas target is compute_103 (family-stable) -> NO tcgen05. Use sm_80-class
// tf32 mma.sync.m16n8k8 implicit GEMM with cp.async double buffering.
//
// GEMM view: D[Cout, L] = sum over 9 taps of Wt[tap] @ Xshift[tap],
//   K = 128 channels per tap, chunked 32 at a time (36 chunks total).
// CTA tile 128(Cout) x 128(pos); 8 warps (2x4), warp tile 64x32.
// ---------------------------------------------------------------------------

#define CIN    128
#define HWD    56
#define LSP    3136            // 56*56
#define COUT   256
#define NIMG   16
#define LTOT   (NIMG * LSP)    // 50176
#define TM     128
#define TN     128
#define NT     (LTOT / TN)     // 392 spatial tiles
#define SA     36              // padded smem row stride (floats)
#define CHK    32              // K chunk (channels)
#define NCHUNK 36              // 9 taps * 4 chunks
#define BUFF   (TM * SA)       // 4608 floats: one A or B tile
#define BUFSZ  (2 * BUFF)      // 9216 floats: A+B for one buffer
#define SMEMB  (2 * BUFSZ * 4) // 73728 bytes (double buffered)

// Weights pre-transposed + tf32-rounded: g_Wt[tap][co][c]
__device__ uint32_t g_Wt[9 * COUT * CIN];

// ---------------------------------------------------------------------------

__device__ __forceinline__ uint32_t f2tf32(float f) {
    uint32_t u;
    asm("cvt.rna.tf32.f32 %0, %1;" : "=r"(u) : "f"(f));
    return u;
}

__device__ __forceinline__ void cpa16(uint32_t d, const void* s) {
    asm volatile("cp.async.cg.shared.global [%0], [%1], 16;"
                 :: "r"(d), "l"(s));
}

__device__ __forceinline__ void cpa4(uint32_t d, const void* s, uint32_t sz) {
    // sz = 4 (copy) or 0 (zero-fill, no read)
    asm volatile("cp.async.ca.shared.global [%0], [%1], 4, %2;"
                 :: "r"(d), "l"(s), "r"(sz));
}

__device__ __forceinline__ void mma_tf32(float* d, const uint32_t* a,
                                         const uint32_t* b) {
    asm volatile(
        "mma.sync.aligned.m16n8k8.row.col.f32.tf32.tf32.f32 "
        "{%0,%1,%2,%3}, {%4,%5,%6,%7}, {%8,%9}, {%0,%1,%2,%3};"
        : "+f"(d[0]), "+f"(d[1]), "+f"(d[2]), "+f"(d[3])
        : "r"(a[0]), "r"(a[1]), "r"(a[2]), "r"(a[3]),
          "r"(b[0]), "r"(b[1]));
}

// ---------------------------------------------------------------------------
// w[co][c][3][3] fp32 -> g_Wt[tap][co][c] tf32 bits (rna)
// ---------------------------------------------------------------------------
__global__ void wt_transform_kernel(const float* __restrict__ w) {
    int idx = blockIdx.x * blockDim.x + threadIdx.x;
    if (idx < 9 * COUT * CIN) {
        int ij = idx >> 15;            // tap
        int r  = idx & 32767;
        int co = r >> 7;
        int c  = r & 127;
        g_Wt[idx] = f2tf32(w[(co * CIN + c) * 9 + ij]);
    }
}

// ---------------------------------------------------------------------------
// Main kernel
// ---------------------------------------------------------------------------
__global__ void __launch_bounds__(256, 2)
conv_mma_kernel(const float* __restrict__ x,
                const float* __restrict__ bias,
                float* __restrict__ out) {
    extern __shared__ float smem[];
    uint32_t sb;
    asm("{ .reg .u64 t; cvta.to.shared.u64 t, %1; cvt.u32.u64 %0, t; }"
        : "=r"(sb) : "l"(smem));

    const int tid  = threadIdx.x;
    const int wid  = tid >> 5;
    const int lane = tid & 31;
    const int wm   = wid >> 2;          // 0..1: 64-row warp band
    const int wn   = wid & 3;           // 0..3: 32-col warp band
    const int g    = lane >> 2;         // group id (row within m8/n8)
    const int tig  = lane & 3;          // thread-in-group (k / 2n index)

    const int mtile = blockIdx.y;       // 0..1 (Cout half)
    const int l0    = blockIdx.x * TN;  // global position base

    // ---- A loader: 4 x 16B cp.async per thread per chunk ----
    const int a_cob = tid >> 3;         // + i*32 -> co
    const int a_chq = tid & 7;          // 16B sub-block within 32ch row
    const uint32_t* wrow0 =
        g_Wt + (size_t)(mtile * TM) * CIN;

    // ---- B loader: one position per thread, 16 channels (stride 2) ----
    const int pos = tid & 127;
    const int chb = tid >> 7;           // 0 or 1
    const int l   = l0 + pos;
    const int img = l / LSP;
    const int rl  = l - img * LSP;
    const int oh  = rl / HWD;
    const int ow  = rl - oh * HWD;
    const float* xb = x + (size_t)img * CIN * LSP;

    // fragment LDS bases (float indices)
    const int abase = (wm * 64 + g) * SA + tig;
    const int bbase = (wn * 32 + g) * SA + tig;

    float acc[4][4][4];
    #pragma unroll
    for (int mi = 0; mi < 4; ++mi)
        #pragma unroll
        for (int ni = 0; ni < 4; ++ni)
            #pragma unroll
            for (int r2 = 0; r2 < 4; ++r2)
                acc[mi][ni][r2] = 0.0f;

    // prefetch lambda: chunk q into buffer pbuf
    auto prefetch = [&](int q, int pbuf) {
        const int tap = q >> 2;
        const int c0  = (q & 3) * CHK;
        const int ki  = tap / 3;
        const int kj  = tap - ki * 3;
        // A: [128 co][32 ch] contiguous 16B rows
        const uint32_t* wsrc = wrow0 + (size_t)tap * (COUT * CIN) + c0;
        const uint32_t adst0 = sb + (uint32_t)(pbuf * BUFSZ) * 4u;
        #pragma unroll
        for (int i = 0; i < 4; ++i) {
            int co = i * 32 + a_cob;
            cpa16(adst0 + (uint32_t)(co * SA + a_chq * 4) * 4u,
                  wsrc + (size_t)co * CIN + a_chq * 4);
        }
        // B: [128 pos][32 ch] gathered, zero-filled at padding
        const int ih = oh + ki - 1;
        const int iw = ow + kj - 1;
        const bool valid = ((unsigned)ih < HWD) & ((unsigned)iw < HWD);
        const float* src = valid
            ? (xb + (size_t)(c0 + chb) * LSP + ih * HWD + iw) : x;
        const uint32_t sz = valid ? 4u : 0u;
        uint32_t bdst = sb + (uint32_t)(pbuf * BUFSZ + BUFF + pos * SA + chb) * 4u;
        #pragma unroll
        for (int i = 0; i < 16; ++i) {
            cpa4(bdst + (uint32_t)(i * 8), src + (size_t)(2 * i) * LSP, sz);
        }
    };

    // compute lambda: consume buffer cbuf
    auto compute = [&](int cbuf) {
        const uint32_t* Ab = (const uint32_t*)(smem + cbuf * BUFSZ);
        const float*    Bb = smem + cbuf * BUFSZ + BUFF;
        #pragma unroll
        for (int ks = 0; ks < 4; ++ks) {
            uint32_t Af[4][4];
            #pragma unroll
            for (int mi = 0; mi < 4; ++mi) {
                int a0 = abase + mi * 16 * SA + ks * 8;
                Af[mi][0] = Ab[a0];
                Af[mi][1] = Ab[a0 + 8 * SA];
                Af[mi][2] = Ab[a0 + 4];
                Af[mi][3] = Ab[a0 + 8 * SA + 4];
            }
            uint32_t Bf[4][2];
            #pragma unroll
            for (int ni = 0; ni < 4; ++ni) {
                int b0 = bbase + ni * 8 * SA + ks * 8;
                Bf[ni][0] = f2tf32(Bb[b0]);
                Bf[ni][1] = f2tf32(Bb[b0 + 4]);
            }
            #pragma unroll
            for (int mi = 0; mi < 4; ++mi)
                #pragma unroll
                for (int ni = 0; ni < 4; ++ni)
                    mma_tf32(acc[mi][ni], Af[mi], Bf[ni]);
        }
    };

    // ---- pipelined main loop ----
    prefetch(0, 0);
    asm volatile("cp.async.commit_group;" ::: "memory");
    #pragma unroll 1
    for (int q = 0; q < NCHUNK; ++q) {
        if (q + 1 < NCHUNK) {
            prefetch(q + 1, (q + 1) & 1);
            asm volatile("cp.async.commit_group;" ::: "memory");
            asm volatile("cp.async.wait_group 1;" ::: "memory");
        } else {
            asm volatile("cp.async.wait_group 0;" ::: "memory");
        }
        __syncthreads();
        compute(q & 1);
        __syncthreads();
    }

    // ---- epilogue: +bias, float2 stores (l always even, LSP even ->
    //      a (l, l+1) pair never crosses an image boundary) ----
    const int co_base = mtile * TM + wm * 64 + g;
    float bv[4][2];
    #pragma unroll
    for (int mi = 0; mi < 4; ++mi) {
        bv[mi][0] = bias[co_base + mi * 16];
        bv[mi][1] = bias[co_base + mi * 16 + 8];
    }
    #pragma unroll
    for (int ni = 0; ni < 4; ++ni) {
        const int le   = l0 + wn * 32 + ni * 8 + 2 * tig;
        const int im2  = le / LSP;
        const int rle  = le - im2 * LSP;
        float* obase = out + (size_t)im2 * COUT * LSP + rle;
        #pragma unroll
        for (int mi = 0; mi < 4; ++mi) {
            #pragma unroll
            for (int h = 0; h < 2; ++h) {
                const int co = co_base + mi * 16 + h * 8;
                float2 v;
                v.x = acc[mi][ni][h * 2 + 0] + bv[mi][h];
                v.y = acc[mi][ni][h * 2 + 1] + bv[mi][h];
                *reinterpret_cast<float2*>(obase + (size_t)co * LSP) = v;
            }
        }
    }
}

// ---------------------------------------------------------------------------

extern "C" void kernel_launch(void* const* d_in, const int* in_sizes, int n_in,
                              void* d_out, int out_size) {
    const float* x    = (const float*)d_in[0];   // [16,128,56,56]
    const float* w    = (const float*)d_in[1];   // [256,128,3,3]
    const float* bias = (const float*)d_in[2];   // [256]
    float* out = (float*)d_out;                  // [16,256,56,56]

    cudaFuncSetAttribute(conv_mma_kernel,
                         cudaFuncAttributeMaxDynamicSharedMemorySize, SMEMB);

    wt_transform_kernel<<<(9 * COUT * CIN + 255) / 256, 256>>>(w);
    dim3 grid(NT, 2, 1);
    conv_mma_kernel<<<grid, 256, SMEMB>>>(x, bias, out);
}

// round 5
// speedup vs baseline: 1.2134x; 1.2134x over previous
#include <cuda_runtime.h>
#include <cstdint>

// ---------------------------------------------------------------------------
// AnalogConv2d: 3x3 s1 p1, N=16 C=128 H=W=56 Cout=256, fp32 + bias.
// tf32 mma.sync.m16n8k8 implicit GEMM (compute_103-safe; no tcgen05).
// CTA tile 256(Cout) x 128(pos), 8 warps (4Mx2N), warp tile 64x64.
// K = 9 taps * 128 ch, chunked 32; 4-stage cp.async pipeline.
// A staged fragment-major (1 LDS.128 per fragment); B staged with XOR
// swizzle -> conflict-free STS (lane=pos) AND LDS (g,tig pattern).
// ---------------------------------------------------------------------------

#define CIN    128
#define HWD    56
#define LSP    3136
#define COUT   256
#define NIMG   16
#define LTOT   (NIMG * LSP)      // 50176
#define TM     256
#define TN     128
#define NCTA   (LTOT / TN)       // 392
#define CHK    32
#define NCHUNK 36                // 9 taps * 4
#define STAGES 4
#define A_ST_B 32768u            // 256*32*4
#define B_ST_B 16384u            // 128*32*4
#define STG_B  (A_ST_B + B_ST_B) // 49152
#define SMEMB  (STAGES * STG_B)  // 196608 (192KB)

// Weights: fragment-major tf32: [tap][ck][mfrag16][ks4][lane32][4]
__device__ __align__(256) uint32_t g_Wt[9 * COUT * CIN];

__device__ __forceinline__ uint32_t f2tf32(float f) {
    uint32_t u;
    asm("cvt.rna.tf32.f32 %0, %1;" : "=r"(u) : "f"(f));
    return u;
}
__device__ __forceinline__ void cpa16(uint32_t d, const void* s) {
    asm volatile("cp.async.cg.shared.global [%0], [%1], 16;" :: "r"(d), "l"(s));
}
__device__ __forceinline__ void cpa4(uint32_t d, const void* s, uint32_t sz) {
    asm volatile("cp.async.ca.shared.global [%0], [%1], 4, %2;"
                 :: "r"(d), "l"(s), "r"(sz));
}
__device__ __forceinline__ void mma_tf32(float* d, const uint32_t* a,
                                         const uint32_t* b) {
    asm volatile(
        "mma.sync.aligned.m16n8k8.row.col.f32.tf32.tf32.f32 "
        "{%0,%1,%2,%3}, {%4,%5,%6,%7}, {%8,%9}, {%0,%1,%2,%3};"
        : "+f"(d[0]), "+f"(d[1]), "+f"(d[2]), "+f"(d[3])
        : "r"(a[0]), "r"(a[1]), "r"(a[2]), "r"(a[3]), "r"(b[0]), "r"(b[1]));
}

// ---------------------------------------------------------------------------
// w[co][c][3][3] -> g_Wt fragment-major (tf32 bits).
// idx = ((((tap*4+ck)*16+mf)*4+ks)*32+lane)*4 + r
// r0:(g,tig) r1:(g+8,tig) r2:(g,tig+4) r3:(g+8,tig+4)
// ---------------------------------------------------------------------------
__global__ void wt_transform_kernel(const float* __restrict__ w) {
    int idx = blockIdx.x * blockDim.x + threadIdx.x;
    if (idx >= 9 * COUT * CIN) return;
    int r    = idx & 3;
    int lane = (idx >> 2) & 31;
    int ks   = (idx >> 7) & 3;
    int mf   = (idx >> 9) & 15;
    int ck   = (idx >> 13) & 3;
    int tap  = idx >> 15;
    int g = lane >> 2, tig = lane & 3;
    int co = mf * 16 + g + 8 * (r & 1);
    int c  = ck * 32 + ks * 8 + tig + 4 * (r >> 1);
    g_Wt[idx] = f2tf32(w[(co * CIN + c) * 9 + tap]);
}

// ---------------------------------------------------------------------------
__global__ void __launch_bounds__(256, 1)
conv_mma_kernel(const float* __restrict__ x,
                const float* __restrict__ bias,
                float* __restrict__ out) {
    extern __shared__ float smem[];
    uint32_t sb;
    asm("{ .reg .u64 t; cvta.to.shared.u64 t, %1; cvt.u32.u64 %0, t; }"
        : "=r"(sb) : "l"(smem));

    const int tid  = threadIdx.x;
    const int wid  = tid >> 5;
    const int lane = tid & 31;
    const int wm   = wid >> 1;        // 0..3 : 64-row Cout band
    const int wn   = wid & 1;         // 0..1 : 64-col pos band
    const int g    = lane >> 2;
    const int tig  = lane & 3;

    const int l0 = blockIdx.x * TN;

    // ---- B gather setup: thread -> (pos, chb) ----
    const int pos = tid & 127;
    const int chb = tid >> 7;
    {
        // nothing
    }
    const int l   = l0 + pos;
    const int img = l / LSP;
    const int rl  = l - img * LSP;
    const int oh  = rl / HWD;
    const int ow  = rl - oh * HWD;
    const float* xb = x + (size_t)img * CIN * LSP;
    const uint32_t hsw = ((uint32_t)(pos & 7) << 2) | ((uint32_t)(pos >> 3) & 3);
    const uint32_t bdst_row = (uint32_t)pos * 32u;

    float acc[4][8][4];
    #pragma unroll
    for (int mi = 0; mi < 4; ++mi)
        #pragma unroll
        for (int ni = 0; ni < 8; ++ni)
            #pragma unroll
            for (int r2 = 0; r2 < 4; ++r2)
                acc[mi][ni][r2] = 0.0f;

    auto prefetch = [&](int q, int s) {
        const int tap = q >> 2;
        const int ck  = q & 3;
        const int ki  = tap / 3, kj = tap - ki * 3;
        const uint32_t sbase = sb + (uint32_t)s * STG_B;
        // A: 32KB contiguous fragment-major
        const uint32_t* asrc = g_Wt + tap * 32768 + ck * 8192;
        #pragma unroll
        for (int i = 0; i < 8; ++i)
            cpa16(sbase + (uint32_t)(i * 256 + tid) * 16u,
                  asrc + (i * 256 + tid) * 4);
        // B: gather 16 channels (chb, chb+2, ...), XOR-swizzled dst
        const int ih = oh + ki - 1, iw = ow + kj - 1;
        const bool valid = ((unsigned)ih < HWD) & ((unsigned)iw < HWD);
        const float* src = valid
            ? (xb + (size_t)(ck * 32 + chb) * LSP + ih * HWD + iw) : x;
        const uint32_t sz = valid ? 4u : 0u;
        const uint32_t bb = sbase + A_ST_B;
        #pragma unroll
        for (int i = 0; i < 16; ++i) {
            uint32_t ch = (uint32_t)(chb + 2 * i);
            cpa4(bb + (bdst_row + (ch ^ hsw)) * 4u,
                 src + (size_t)(2 * i) * LSP, sz);
        }
    };

    auto compute = [&](int s) {
        const float4* A4 = (const float4*)(smem + s * (STG_B / 4));
        const float*  Bb = smem + s * (STG_B / 4) + (A_ST_B / 4);
        const uint32_t g4 = (uint32_t)g << 2;
        #pragma unroll
        for (int ks = 0; ks < 4; ++ks) {
            float4 af[4];
            #pragma unroll
            for (int mi = 0; mi < 4; ++mi)
                af[mi] = A4[((wm * 4 + mi) * 4 + ks) * 32 + lane];
            uint32_t bf[8][2];
            #pragma unroll
            for (int ni = 0; ni < 8; ++ni) {
                const uint32_t row = (uint32_t)(wn * 64 + ni * 8 + g) * 32u;
                const uint32_t sw  = g4 | (uint32_t)(ni & 3);
                const uint32_t k0  = (uint32_t)(ks * 8 + tig);
                bf[ni][0] = f2tf32(Bb[row + (k0 ^ sw)]);
                bf[ni][1] = f2tf32(Bb[row + ((k0 + 4) ^ sw)]);
            }
            #pragma unroll
            for (int mi = 0; mi < 4; ++mi) {
                uint32_t a_[4] = { __float_as_uint(af[mi].x),
                                   __float_as_uint(af[mi].y),
                                   __float_as_uint(af[mi].z),
                                   __float_as_uint(af[mi].w) };
                #pragma unroll
                for (int ni = 0; ni < 8; ++ni)
                    mma_tf32(acc[mi][ni], a_, bf[ni]);
            }
        }
    };

    // ---- 4-stage pipeline ----
    #pragma unroll
    for (int s = 0; s < STAGES - 1; ++s) {
        prefetch(s, s);
        asm volatile("cp.async.commit_group;" ::: "memory");
    }
    #pragma unroll 1
    for (int q = 0; q < NCHUNK; ++q) {
        asm volatile("cp.async.wait_group %0;" :: "n"(STAGES - 2) : "memory");
        __syncthreads();
        if (q + STAGES - 1 < NCHUNK)
            prefetch(q + STAGES - 1, (q + STAGES - 1) & (STAGES - 1));
        asm volatile("cp.async.commit_group;" ::: "memory");
        compute(q & (STAGES - 1));
    }

    // ---- epilogue: +bias, float2 stores ----
    const int co_base = wm * 64 + g;
    float bv[4][2];
    #pragma unroll
    for (int mi = 0; mi < 4; ++mi) {
        bv[mi][0] = bias[co_base + mi * 16];
        bv[mi][1] = bias[co_base + mi * 16 + 8];
    }
    #pragma unroll
    for (int ni = 0; ni < 8; ++ni) {
        const int le  = l0 + wn * 64 + ni * 8 + 2 * tig;
        const int im2 = le / LSP;
        const int rle = le - im2 * LSP;
        float* ob = out + (size_t)im2 * COUT * LSP + rle;
        #pragma unroll
        for (int mi = 0; mi < 4; ++mi) {
            #pragma unroll
            for (int h = 0; h < 2; ++h) {
                const int co = co_base + mi * 16 + h * 8;
                float2 v;
                v.x = acc[mi][ni][h * 2 + 0] + bv[mi][h];
                v.y = acc[mi][ni][h * 2 + 1] + bv[mi][h];
                *reinterpret_cast<float2*>(ob + (size_t)co * LSP) = v;
            }
        }
    }
}

// ---------------------------------------------------------------------------
extern "C" void kernel_launch(void* const* d_in, const int* in_sizes, int n_in,
                              void* d_out, int out_size) {
    const float* x    = (const float*)d_in[0];
    const float* w    = (const float*)d_in[1];
    const float* bias = (const float*)d_in[2];
    float* out = (float*)d_out;

    cudaFuncSetAttribute(conv_mma_kernel,
                         cudaFuncAttributeMaxDynamicSharedMemorySize, SMEMB);

    wt_transform_kernel<<<(9 * COUT * CIN + 255) / 256, 256>>>(w);
    conv_mma_kernel<<<NCTA, 256, SMEMB>>>(x, bias, out);
}